// round 16
// baseline (speedup 1.0000x reference)
#include <cuda_runtime.h>
#include <cuda_bf16.h>
#include <math.h>

namespace {

constexpr int B  = 256;
constexpr int L  = 128;
constexpr int H  = 512;
constexpr int H4 = 2048;
constexpr int ENC_CTAS = 512;

// ---------------- device state (allocation-free scratch) ----------------
__device__ __nv_bfloat16 g_hh[2][B * H];                 // hidden (bf16), dbl buf
__device__ float g_c[B * H];                             // cell (fp32)
__device__ __nv_bfloat16 g_enc_outh[(size_t)B * L * H];  // bf16 [b*L+l][h]
__device__ __nv_bfloat16 g_enc_w1h[(size_t)B * L * H];   // bf16 [b*L+l][h]
__device__ __nv_bfloat16 g_ctxh[B * H];                  // attention context (bf16)
__device__ float g_dec_in[2][B];                         // decoder scalar input
__device__ __nv_bfloat16 g_ew4h[H4 * H];                 // enc_Wh bf16, gate-interleaved n'=4h+g
__device__ float g_eb4[H4];
__device__ float g_ewi4[H4];
__device__ __nv_bfloat16 g_dw4h[H4 * 1024];              // dec [Wi(ctx)|Wh] bf16, interleaved
__device__ float g_db4[H4];
__device__ float g_dwi4[H4];
__device__ __nv_bfloat16 g_w1h[H * H];
__device__ __nv_bfloat16 g_w2h[H * H];
__device__ float g_zpart[4 * B * H4];                    // split-K partials
__device__ float g_qpart[8 * B * H];
__device__ unsigned g_bcnt;                              // persistent-kernel barrier counter

// ---------------- math helpers ----------------
__device__ __forceinline__ float sigmoid_acc(float x) {
    return 1.0f / (1.0f + __expf(-x));
}
__device__ __forceinline__ float tanh_acc(float x) {
    float e = __expf(-2.0f * fabsf(x));
    float r = (1.0f - e) / (1.0f + e);
    return copysignf(r, x);
}
__device__ __forceinline__ float tanh_fast(float x) {
    float y;
    asm("tanh.approx.f32 %0, %1;" : "=f"(y) : "f"(x));
    return y;
}
__device__ __forceinline__ void mma_bf16(float c[4], const unsigned a[4], const unsigned b[2]) {
    asm("mma.sync.aligned.m16n8k16.row.col.f32.bf16.bf16.f32 "
        "{%0,%1,%2,%3},{%4,%5,%6,%7},{%8,%9},{%0,%1,%2,%3};"
        : "+f"(c[0]), "+f"(c[1]), "+f"(c[2]), "+f"(c[3])
        : "r"(a[0]), "r"(a[1]), "r"(a[2]), "r"(a[3]), "r"(b[0]), "r"(b[1]));
}

// Monotonic-counter grid barrier: all CTAs co-resident (guaranteed by launch bounds).
__device__ __forceinline__ void grid_bar(unsigned target) {
    __threadfence();
    __syncthreads();
    if (threadIdx.x == 0) {
        atomicAdd(&g_bcnt, 1u);
        while (*(volatile unsigned*)&g_bcnt < target) { }
        __threadfence();
    }
    __syncthreads();
}

// ---------------- init ----------------
__global__ void k_init() {
    int i = blockIdx.x * blockDim.x + threadIdx.x;
    int stride = gridDim.x * blockDim.x;
    const __nv_bfloat16 z0 = __float2bfloat16(0.0f);
    for (int j = i; j < B * H; j += stride) {
        g_hh[0][j] = z0;
        g_c[j]     = 0.0f;
    }
    if (i < B) g_dec_in[0][i] = 0.0f;
    if (i == 0) g_bcnt = 0;
}

// ---------------- one-time repacks ----------------
__global__ void k_repack_enc(const float* __restrict__ ewh,
                             const float* __restrict__ eb,
                             const float* __restrict__ ewi) {
    int i = blockIdx.x * blockDim.x + threadIdx.x;
    int stride = gridDim.x * blockDim.x;
    for (int j = i; j < H4 * H; j += stride) {
        int np = j >> 9;
        int k  = j & (H - 1);
        int hh = np >> 2, g = np & 3;
        g_ew4h[j] = __float2bfloat16_rn(ewh[(g * H + hh) * H + k]);
    }
    if (i < H4) {
        int hh = i >> 2, g = i & 3;
        g_eb4[i]  = eb[g * H + hh];
        g_ewi4[i] = ewi[g * H + hh];
    }
}

__global__ void k_repack_dec(const float* __restrict__ dwi,
                             const float* __restrict__ dwh,
                             const float* __restrict__ db) {
    int i = blockIdx.x * blockDim.x + threadIdx.x;
    int stride = gridDim.x * blockDim.x;
    for (int j = i; j < H4 * 1024; j += stride) {
        int np = j >> 10;
        int k  = j & 1023;
        int hh = np >> 2, g = np & 3;
        int row = g * H + hh;
        float v = (k < H) ? dwi[row * (H + 1) + k] : dwh[row * H + (k - H)];
        g_dw4h[j] = __float2bfloat16_rn(v);
    }
    if (i < H4) {
        int hh = i >> 2, g = i & 3;
        g_db4[i]  = db[g * H + hh];
        g_dwi4[i] = dwi[(g * H + hh) * (H + 1) + H];
    }
}

__global__ void k_repack_w(const float* __restrict__ w1, const float* __restrict__ w2) {
    int i = blockIdx.x * blockDim.x + threadIdx.x;
    int stride = gridDim.x * blockDim.x;
    for (int j = i; j < H * H; j += stride) {
        g_w1h[j] = __float2bfloat16_rn(w1[j]);
        g_w2h[j] = __float2bfloat16_rn(w2[j]);
    }
}

// ======================================================================================
// bf16 tensor-core GEMM (R15 core, proven): part[kz] = A @ W^T over K-chunk (m16n8k16).
// ======================================================================================
template <int KTOT, int KS, bool CONCAT, int EPI>
__global__ void __launch_bounds__(128) k_mma(
    const __nv_bfloat16* __restrict__ W,     // [N x KTOT] bf16
    const __nv_bfloat16* __restrict__ A0,
    const __nv_bfloat16* __restrict__ A1,
    float* __restrict__ part)                // [KS][256][N]
{
    constexpr int KC  = KTOT / KS;
    constexpr int NST = KC / 32;
    constexpr int PAD = 20;

    __shared__ unsigned As[2][64][PAD];
    __shared__ unsigned Bs[2][64][PAD];

    const int tid  = threadIdx.x;
    const int warp = tid >> 5;
    const int lane = tid & 31;
    const int mw   = (warp >> 1) * 32;
    const int nw   = (warp & 1) * 32;
    const int n0   = blockIdx.x * 64;
    const int m0   = blockIdx.y * 64;
    const int kb   = blockIdx.z * KC;
    const int N    = gridDim.x * 64;

    const int lr = tid >> 2;
    const int lq = tid & 3;

    float c[2][4][4] = {};

    uint4 a_r[2], w_r[2];
    auto gload = [&](int k0) {
        const int k = kb + k0 + lq * 8;
#pragma unroll
        for (int hh = 0; hh < 2; hh++) {
            const int row = lr + hh * 32;
            const __nv_bfloat16* ap;
            if (CONCAT) {
                ap = (k < 512) ? &A0[(m0 + row) * 512 + k]
                               : &A1[(m0 + row) * 512 + (k - 512)];
            } else {
                ap = &A0[(size_t)(m0 + row) * 512 + k];
            }
            a_r[hh] = *(const uint4*)ap;
            w_r[hh] = *(const uint4*)&W[(size_t)(n0 + row) * KTOT + k];
        }
    };
    auto sstore = [&](int buf) {
#pragma unroll
        for (int hh = 0; hh < 2; hh++) {
            const int row = lr + hh * 32;
            As[buf][row][0 * 4 + lq] = a_r[hh].x;
            As[buf][row][1 * 4 + lq] = a_r[hh].y;
            As[buf][row][2 * 4 + lq] = a_r[hh].z;
            As[buf][row][3 * 4 + lq] = a_r[hh].w;
            Bs[buf][row][0 * 4 + lq] = w_r[hh].x;
            Bs[buf][row][1 * 4 + lq] = w_r[hh].y;
            Bs[buf][row][2 * 4 + lq] = w_r[hh].z;
            Bs[buf][row][3 * 4 + lq] = w_r[hh].w;
        }
    };

    gload(0);
    sstore(0);
    __syncthreads();

    for (int st = 0; st < NST; st++) {
        const bool more = (st + 1 < NST);
        if (more) gload((st + 1) * 32);

        const int cb = st & 1;
#pragma unroll
        for (int s = 0; s < 2; s++) {
            const int cidx = ((lane & 3) << 2) + s * 2;
            const int rq = lane >> 2;
            unsigned af[2][4], bfr[4][2];
#pragma unroll
            for (int mt = 0; mt < 2; mt++) {
                const int r = mw + mt * 16 + rq;
                uint2 lo = *(const uint2*)&As[cb][r][cidx];
                uint2 hi = *(const uint2*)&As[cb][r + 8][cidx];
                af[mt][0] = lo.x; af[mt][1] = hi.x;
                af[mt][2] = lo.y; af[mt][3] = hi.y;
            }
#pragma unroll
            for (int nt = 0; nt < 4; nt++) {
                const int nc = nw + nt * 8 + rq;
                uint2 bb = *(const uint2*)&Bs[cb][nc][cidx];
                bfr[nt][0] = bb.x; bfr[nt][1] = bb.y;
            }
#pragma unroll
            for (int mt = 0; mt < 2; mt++)
#pragma unroll
                for (int nt = 0; nt < 4; nt++)
                    mma_bf16(c[mt][nt], af[mt], bfr[nt]);
        }
        if (more) sstore(cb ^ 1);
        __syncthreads();
    }

#pragma unroll
    for (int mt = 0; mt < 2; mt++) {
#pragma unroll
        for (int nt = 0; nt < 4; nt++) {
            const int m = m0 + mw + mt * 16 + (lane >> 2);
            const int n = n0 + nw + nt * 8 + ((lane & 3) << 1);
            if (EPI == 0) {
                float* dst = part + (size_t)blockIdx.z * 256 * N;
                *(float2*)&dst[(size_t)m * N + n]       = make_float2(c[mt][nt][0], c[mt][nt][1]);
                *(float2*)&dst[(size_t)(m + 8) * N + n] = make_float2(c[mt][nt][2], c[mt][nt][3]);
            } else {
                __nv_bfloat162 p0 = __floats2bfloat162_rn(c[mt][nt][0], c[mt][nt][1]);
                __nv_bfloat162 p1 = __floats2bfloat162_rn(c[mt][nt][2], c[mt][nt][3]);
                *(unsigned*)&g_enc_w1h[(size_t)m * H + n]       = *(unsigned*)&p0;
                *(unsigned*)&g_enc_w1h[(size_t)(m + 8) * H + n] = *(unsigned*)&p1;
            }
        }
    }
}

// ======================================================================================
// PERSISTENT ENCODER: 512 CTAs x 128 threads, co-resident (4 CTAs/SM guaranteed).
// Per step: bf16 GEMM phase (R15 body, tile map = (32,4,4)) -> grid barrier ->
// gates phase (2 (b,h) elems per thread) -> grid barrier. One launch for 128 steps.
// ======================================================================================
__global__ void __launch_bounds__(128, 4) k_enc_persist(const int* __restrict__ xs) {
    constexpr int PAD = 20;
    __shared__ unsigned As[2][64][PAD];
    __shared__ unsigned Bs[2][64][PAD];

    const int tid  = threadIdx.x;
    const int warp = tid >> 5;
    const int lane = tid & 31;
    const int mw   = (warp >> 1) * 32;
    const int nw   = (warp & 1) * 32;

    const int bx = blockIdx.x & 31;          // n-tile
    const int by = (blockIdx.x >> 5) & 3;    // m-tile
    const int kz = blockIdx.x >> 7;          // split-K chunk
    const int n0 = bx * 64;
    const int m0 = by * 64;
    const int kb = kz * 128;                 // KC = 128

    const int lr = tid >> 2;
    const int lq = tid & 3;
    const int gtid = blockIdx.x * 128 + tid; // 0..65535

    unsigned bt = 0;

    for (int t = 0; t < L; t++) {
        const int p = t & 1;
        const __nv_bfloat16* A0 = g_hh[p];

        // ---------------- GEMM phase (KTOT=512, KS=4 -> NST=4) ----------------
        float c[2][4][4] = {};
        uint4 a_r[2], w_r[2];
        auto gload = [&](int k0) {
            const int k = kb + k0 + lq * 8;
#pragma unroll
            for (int hh = 0; hh < 2; hh++) {
                const int row = lr + hh * 32;
                a_r[hh] = *(const uint4*)&A0[(m0 + row) * 512 + k];
                w_r[hh] = *(const uint4*)&g_ew4h[(size_t)(n0 + row) * 512 + k];
            }
        };
        auto sstore = [&](int buf) {
#pragma unroll
            for (int hh = 0; hh < 2; hh++) {
                const int row = lr + hh * 32;
                As[buf][row][0 * 4 + lq] = a_r[hh].x;
                As[buf][row][1 * 4 + lq] = a_r[hh].y;
                As[buf][row][2 * 4 + lq] = a_r[hh].z;
                As[buf][row][3 * 4 + lq] = a_r[hh].w;
                Bs[buf][row][0 * 4 + lq] = w_r[hh].x;
                Bs[buf][row][1 * 4 + lq] = w_r[hh].y;
                Bs[buf][row][2 * 4 + lq] = w_r[hh].z;
                Bs[buf][row][3 * 4 + lq] = w_r[hh].w;
            }
        };

        gload(0);
        sstore(0);
        __syncthreads();

#pragma unroll 1
        for (int st = 0; st < 4; st++) {
            const bool more = (st + 1 < 4);
            if (more) gload((st + 1) * 32);
            const int cb = st & 1;
#pragma unroll
            for (int s = 0; s < 2; s++) {
                const int cidx = ((lane & 3) << 2) + s * 2;
                const int rq = lane >> 2;
                unsigned af[2][4], bfr[4][2];
#pragma unroll
                for (int mt = 0; mt < 2; mt++) {
                    const int r = mw + mt * 16 + rq;
                    uint2 lo = *(const uint2*)&As[cb][r][cidx];
                    uint2 hi = *(const uint2*)&As[cb][r + 8][cidx];
                    af[mt][0] = lo.x; af[mt][1] = hi.x;
                    af[mt][2] = lo.y; af[mt][3] = hi.y;
                }
#pragma unroll
                for (int nt = 0; nt < 4; nt++) {
                    const int nc = nw + nt * 8 + rq;
                    uint2 bb = *(const uint2*)&Bs[cb][nc][cidx];
                    bfr[nt][0] = bb.x; bfr[nt][1] = bb.y;
                }
#pragma unroll
                for (int mt = 0; mt < 2; mt++)
#pragma unroll
                    for (int nt = 0; nt < 4; nt++)
                        mma_bf16(c[mt][nt], af[mt], bfr[nt]);
            }
            if (more) sstore(cb ^ 1);
            __syncthreads();
        }

#pragma unroll
        for (int mt = 0; mt < 2; mt++) {
#pragma unroll
            for (int nt = 0; nt < 4; nt++) {
                const int m = m0 + mw + mt * 16 + (lane >> 2);
                const int n = n0 + nw + nt * 8 + ((lane & 3) << 1);
                float* dst = g_zpart + (size_t)kz * (B * H4);
                *(float2*)&dst[(size_t)m * H4 + n]       = make_float2(c[mt][nt][0], c[mt][nt][1]);
                *(float2*)&dst[(size_t)(m + 8) * H4 + n] = make_float2(c[mt][nt][2], c[mt][nt][3]);
            }
        }

        bt += ENC_CTAS;
        grid_bar(bt);

        // ---------------- gates phase: 2 (b,h) elements per thread ----------------
#pragma unroll
        for (int r = 0; r < 2; r++) {
            const int idx = gtid + r * 65536;    // 0..131071
            const int b = idx >> 9;
            const int h = idx & (H - 1);
            const int np = h << 2;

            const float xb = (float)xs[b * L + t];

            float zx = 0.f, zy = 0.f, zz = 0.f, zw = 0.f;
#pragma unroll
            for (int kk = 0; kk < 4; kk++) {
                float4 z = *(const float4*)&g_zpart[(size_t)kk * (B * H4) + (size_t)b * H4 + np];
                zx += z.x; zy += z.y; zz += z.z; zw += z.w;
            }
            const float4 bb = *(const float4*)&g_eb4[np];
            const float4 ww = *(const float4*)&g_ewi4[np];

            const float zi = zx + bb.x + xb * ww.x;
            const float zf = zy + bb.y + xb * ww.y;
            const float zg = zz + bb.z + xb * ww.z;
            const float zo = zw + bb.w + xb * ww.w;

            const float cc = sigmoid_acc(zf) * g_c[idx] + sigmoid_acc(zi) * tanh_acc(zg);
            const float hn = sigmoid_acc(zo) * tanh_acc(cc);
            g_c[idx] = cc;
            const __nv_bfloat16 hb = __float2bfloat16_rn(hn);
            g_hh[p ^ 1][idx] = hb;
            g_enc_outh[((size_t)b * L + t) * H + h] = hb;
        }

        bt += ENC_CTAS;
        grid_bar(bt);
    }
}

// ---------------- gates (decoder, standalone) ----------------
template <int KZ>
__global__ void __launch_bounds__(256) k_gates_dec(
    const int* __restrict__ xs,
    const int* __restrict__ argsort,
    int t)
{
    const int idx = blockIdx.x * 256 + threadIdx.x;
    const int b = idx >> 9;
    const int h = idx & (H - 1);
    const int np = h << 2;
    const int p = t & 1;

    const float xb = g_dec_in[p][b];

    float zx = 0.f, zy = 0.f, zz = 0.f, zw = 0.f;
#pragma unroll
    for (int kz = 0; kz < KZ; kz++) {
        float4 z = *(const float4*)&g_zpart[(size_t)kz * (B * H4) + (size_t)b * H4 + np];
        zx += z.x; zy += z.y; zz += z.z; zw += z.w;
    }
    const float4 bb = *(const float4*)&g_db4[np];
    const float4 ww = *(const float4*)&g_dwi4[np];

    const float zi = zx + bb.x + xb * ww.x;
    const float zf = zy + bb.y + xb * ww.y;
    const float zg = zz + bb.z + xb * ww.z;
    const float zo = zw + bb.w + xb * ww.w;

    const float c  = sigmoid_acc(zf) * g_c[idx] + sigmoid_acc(zi) * tanh_acc(zg);
    const float hn = sigmoid_acc(zo) * tanh_acc(c);
    g_c[idx] = c;
    g_hh[p ^ 1][idx] = __float2bfloat16_rn(hn);
    if (h == 0) {
        g_dec_in[p ^ 1][b] = (float)xs[b * L + argsort[b * L + t]];
    }
}

// ---------------- attention (proven): q-reduce + scores + softmax + context ---------------
__global__ void __launch_bounds__(256) k_attn(const float* __restrict__ vt,
                                              float* __restrict__ out, int t) {
    __shared__ float q_s[H];
    __shared__ float vt_s[H];
    __shared__ float sc[L];
    __shared__ float aj[L];

    const int b = blockIdx.x;
    const int tid = threadIdx.x;
    const int lane = tid & 31;
    const int w = tid >> 5;

    for (int i = tid; i < H; i += 256) {
        float s = 0.0f;
#pragma unroll
        for (int sp = 0; sp < 8; sp++)
            s += g_qpart[(size_t)sp * (B * H) + b * H + i];
        q_s[i]  = s;
        vt_s[i] = vt[i];
    }
    __syncthreads();

#pragma unroll 1
    for (int li = 0; li < 16; li++) {
        const int l = w * 16 + li;
        const uint4* e8 = (const uint4*)(g_enc_w1h + (size_t)(b * L + l) * H);
        float s = 0.f;
#pragma unroll
        for (int j = 0; j < 2; j++) {
            const int base = (lane + j * 32) * 8;
            uint4 u = e8[lane + j * 32];
            float4 q0 = *(const float4*)&q_s[base];
            float4 q1 = *(const float4*)&q_s[base + 4];
            float4 v0 = *(const float4*)&vt_s[base];
            float4 v1 = *(const float4*)&vt_s[base + 4];
            float2 e0 = __bfloat1622float2(*(__nv_bfloat162*)&u.x);
            float2 e1 = __bfloat1622float2(*(__nv_bfloat162*)&u.y);
            float2 e2 = __bfloat1622float2(*(__nv_bfloat162*)&u.z);
            float2 e3 = __bfloat1622float2(*(__nv_bfloat162*)&u.w);
            s += v0.x * tanh_fast(e0.x + q0.x);
            s += v0.y * tanh_fast(e0.y + q0.y);
            s += v0.z * tanh_fast(e1.x + q0.z);
            s += v0.w * tanh_fast(e1.y + q0.w);
            s += v1.x * tanh_fast(e2.x + q1.x);
            s += v1.y * tanh_fast(e2.y + q1.y);
            s += v1.z * tanh_fast(e3.x + q1.z);
            s += v1.w * tanh_fast(e3.y + q1.w);
        }
#pragma unroll
        for (int o = 16; o > 0; o >>= 1) s += __shfl_xor_sync(0xffffffffu, s, o);
        if (lane == 0) sc[l] = s;
    }
    __syncthreads();

    if (w == 0) {
        float sv[4];
        float m = -1e30f;
#pragma unroll
        for (int k = 0; k < 4; k++) { sv[k] = sc[lane * 4 + k]; m = fmaxf(m, sv[k]); }
#pragma unroll
        for (int o = 16; o > 0; o >>= 1) m = fmaxf(m, __shfl_xor_sync(0xffffffffu, m, o));
        float e[4], sum = 0.f;
#pragma unroll
        for (int k = 0; k < 4; k++) { e[k] = __expf(sv[k] - m); sum += e[k]; }
#pragma unroll
        for (int o = 16; o > 0; o >>= 1) sum += __shfl_xor_sync(0xffffffffu, sum, o);
        const float ls  = __logf(sum);
        const float inv = 1.0f / sum;
        float* orow = out + ((size_t)b * L + t) * L;
#pragma unroll
        for (int k = 0; k < 4; k++) {
            orow[lane * 4 + k] = sv[k] - m - ls;
            aj[lane * 4 + k]   = e[k] * inv;
        }
    }
    __syncthreads();

    const int h2 = tid * 2;
    float ax = 0.f, ay = 0.f;
    const __nv_bfloat162* base =
        (const __nv_bfloat162*)(g_enc_outh + (size_t)b * L * H + h2);
#pragma unroll 4
    for (int l = 0; l < L; l++) {
        const float a = aj[l];
        float2 v = __bfloat1622float2(base[(size_t)l * (H / 2)]);
        ax += a * v.x;
        ay += a * v.y;
    }
    __nv_bfloat162 cp = __floats2bfloat162_rn(ax, ay);
    *(__nv_bfloat162*)&g_ctxh[b * H + h2] = cp;
}

}  // namespace

extern "C" void kernel_launch(void* const* d_in, const int* in_sizes, int n_in,
                              void* d_out, int out_size) {
    (void)in_sizes; (void)n_in; (void)out_size;
    const int*   xs      = (const int*)d_in[0];
    const int*   argsort = (const int*)d_in[2];
    const float* enc_Wi  = (const float*)d_in[3];
    const float* enc_Wh  = (const float*)d_in[4];
    const float* enc_b   = (const float*)d_in[5];
    const float* dec_Wi  = (const float*)d_in[6];
    const float* dec_Wh  = (const float*)d_in[7];
    const float* dec_b   = (const float*)d_in[8];
    const float* w1      = (const float*)d_in[9];
    const float* w2      = (const float*)d_in[10];
    const float* vt      = (const float*)d_in[11];
    float* out = (float*)d_out;

    __nv_bfloat16 *p_hh, *p_ctxh, *p_encouth, *p_dw4h, *p_w1h, *p_w2h;
    float *p_zpart, *p_qpart;
    cudaGetSymbolAddress((void**)&p_hh,      g_hh);
    cudaGetSymbolAddress((void**)&p_ctxh,    g_ctxh);
    cudaGetSymbolAddress((void**)&p_encouth, g_enc_outh);
    cudaGetSymbolAddress((void**)&p_dw4h,    g_dw4h);
    cudaGetSymbolAddress((void**)&p_w1h,     g_w1h);
    cudaGetSymbolAddress((void**)&p_w2h,     g_w2h);
    cudaGetSymbolAddress((void**)&p_zpart,   g_zpart);
    cudaGetSymbolAddress((void**)&p_qpart,   g_qpart);

    k_init<<<128, 256>>>();
    k_repack_enc<<<256, 256>>>(enc_Wh, enc_b, enc_Wi);
    k_repack_dec<<<512, 256>>>(dec_Wi, dec_Wh, dec_b);
    k_repack_w<<<256, 256>>>(w1, w2);

    const dim3 gates_grid(B * H / 256);             // 512
    const dim3 lstm_gemm(H4 / 64, B / 64, 4);       // (32, 4, 4) = 512 CTAs
    const dim3 q_gemm(H / 64, B / 64, 8);           // (8, 4, 8)  = 256 CTAs
    const dim3 encw1_grid(H / 64, (B * L) / 64, 1); // (8, 512)

    // ---- encoder: ONE persistent launch for all 128 steps ----
    k_enc_persist<<<ENC_CTAS, 128>>>(xs);

    // ---- hoisted projection enc_w1 = enc_out @ w1^T (bf16 mma, bf16 out) ----
    k_mma<512, 1, false, 1><<<encw1_grid, 128>>>(p_w1h, p_encouth, nullptr, nullptr);

    // ---- decoder: 128 steps of q-proj -> attention -> LSTM GEMM + gates (R15, proven) ----
    for (int t = 0; t < L; t++) {
        const __nv_bfloat16* hp = p_hh + (size_t)(t & 1) * (B * H);
        k_mma<512, 8, false, 0><<<q_gemm, 128>>>(p_w2h, hp, nullptr, p_qpart);
        k_attn<<<B, 256>>>(vt, out, t);
        k_mma<1024, 4, true, 0><<<lstm_gemm, 128>>>(p_dw4h, p_ctxh, hp, p_zpart);
        k_gates_dec<4><<<gates_grid, 256>>>(xs, argsort, t);
    }
}

// round 17
// speedup vs baseline: 1.0540x; 1.0540x over previous
#include <cuda_runtime.h>
#include <cuda_bf16.h>
#include <math.h>

namespace {

constexpr int B  = 256;
constexpr int L  = 128;
constexpr int H  = 512;
constexpr int H4 = 2048;

// ---------------- device state (allocation-free scratch) ----------------
__device__ __nv_bfloat16 g_hh[2][B * H];                 // hidden (bf16, GEMM operand), dbl buf
__device__ float g_c[B * H];                             // cell (fp32)
__device__ __nv_bfloat16 g_enc_outh[(size_t)B * L * H];  // bf16 [b*L+l][h] (encw1 A + attn ctx)
__device__ __nv_bfloat16 g_enc_w1h[(size_t)B * L * H];   // bf16 [b*L+l][h] (attn scores)
__device__ __nv_bfloat16 g_ctxh[B * H];                  // attention context (bf16, GEMM operand)
__device__ float g_dec_in[2][B];                         // decoder scalar input
__device__ __nv_bfloat16 g_ew4h[H4 * H];                 // enc_Wh bf16, gate-interleaved n'=4h+g
__device__ float g_eb4[H4];                              // enc bias, interleaved (fp32)
__device__ float g_ewi4[H4];                             // enc Wi (scalar input), interleaved
__device__ __nv_bfloat16 g_dw4h[H4 * 1024];              // dec [Wi(ctx)|Wh] bf16, interleaved
__device__ float g_db4[H4];
__device__ float g_dwi4[H4];                             // dec Wi last column, interleaved
__device__ __nv_bfloat16 g_w1h[H * H];                   // w1 bf16
__device__ __nv_bfloat16 g_w2h[H * H];                   // w2 bf16
__device__ float g_zpart[4 * B * H4];                    // split-K partials, [kz][b][n'=4h+g]
__device__ float g_qpart[8 * B * H];                     // split-K partials for q

// ---------------- math helpers ----------------
__device__ __forceinline__ float tanh_fast(float x) {
    float y;
    asm("tanh.approx.f32 %0, %1;" : "=f"(y) : "f"(x));
    return y;
}
// sigmoid(x) = 0.5*tanh(x/2) + 0.5 (exact identity; tanh.approx err ~5e-4 abs)
__device__ __forceinline__ float sigmoid_fast(float x) {
    return fmaf(0.5f, tanh_fast(0.5f * x), 0.5f);
}
__device__ __forceinline__ void mma_bf16(float c[4], const unsigned a[4], const unsigned b[2]) {
    asm("mma.sync.aligned.m16n8k16.row.col.f32.bf16.bf16.f32 "
        "{%0,%1,%2,%3},{%4,%5,%6,%7},{%8,%9},{%0,%1,%2,%3};"
        : "+f"(c[0]), "+f"(c[1]), "+f"(c[2]), "+f"(c[3])
        : "r"(a[0]), "r"(a[1]), "r"(a[2]), "r"(a[3]), "r"(b[0]), "r"(b[1]));
}

// ---------------- init ----------------
__global__ void k_init() {
    int i = blockIdx.x * blockDim.x + threadIdx.x;
    int stride = gridDim.x * blockDim.x;
    const __nv_bfloat16 z0 = __float2bfloat16(0.0f);
    for (int j = i; j < B * H; j += stride) {
        g_hh[0][j] = z0;
        g_c[j]     = 0.0f;
    }
    if (i < B) g_dec_in[0][i] = 0.0f;
}

// ---------------- one-time repacks: gate-interleave rows (n' = 4h + g), bf16 weights -------
__global__ void k_repack_enc(const float* __restrict__ ewh,
                             const float* __restrict__ eb,
                             const float* __restrict__ ewi) {
    int i = blockIdx.x * blockDim.x + threadIdx.x;
    int stride = gridDim.x * blockDim.x;
    for (int j = i; j < H4 * H; j += stride) {
        int np = j >> 9;
        int k  = j & (H - 1);
        int hh = np >> 2, g = np & 3;
        g_ew4h[j] = __float2bfloat16_rn(ewh[(g * H + hh) * H + k]);
    }
    if (i < H4) {
        int hh = i >> 2, g = i & 3;
        g_eb4[i]  = eb[g * H + hh];
        g_ewi4[i] = ewi[g * H + hh];
    }
}

__global__ void k_repack_dec(const float* __restrict__ dwi,
                             const float* __restrict__ dwh,
                             const float* __restrict__ db) {
    int i = blockIdx.x * blockDim.x + threadIdx.x;
    int stride = gridDim.x * blockDim.x;
    for (int j = i; j < H4 * 1024; j += stride) {
        int np = j >> 10;
        int k  = j & 1023;
        int hh = np >> 2, g = np & 3;
        int row = g * H + hh;
        float v = (k < H) ? dwi[row * (H + 1) + k] : dwh[row * H + (k - H)];
        g_dw4h[j] = __float2bfloat16_rn(v);
    }
    if (i < H4) {
        int hh = i >> 2, g = i & 3;
        g_db4[i]  = db[g * H + hh];
        g_dwi4[i] = dwi[(g * H + hh) * (H + 1) + H];
    }
}

__global__ void k_repack_w(const float* __restrict__ w1, const float* __restrict__ w2) {
    int i = blockIdx.x * blockDim.x + threadIdx.x;
    int stride = gridDim.x * blockDim.x;
    for (int j = i; j < H * H; j += stride) {
        g_w1h[j] = __float2bfloat16_rn(w1[j]);
        g_w2h[j] = __float2bfloat16_rn(w2[j]);
    }
}

// ======================================================================================
// bf16 tensor-core GEMM (R15 core, proven): part[kz] = A @ W^T over K-chunk (m16n8k16).
// CTA: 128 threads = 4 warps (2x2), tile 64m x 64n; warp tile 32x32.
// k-permuted smem layout -> every mma fragment pair is one aligned LDS.64.
// EPI: 0 = fp32 partials, 1 = bf16 store to g_enc_w1h.
// ======================================================================================
template <int KTOT, int KS, bool CONCAT, int EPI>
__global__ void __launch_bounds__(128) k_mma(
    const __nv_bfloat16* __restrict__ W,     // [N x KTOT] bf16
    const __nv_bfloat16* __restrict__ A0,
    const __nv_bfloat16* __restrict__ A1,
    float* __restrict__ part)                // [KS][256][N]
{
    constexpr int KC  = KTOT / KS;
    constexpr int NST = KC / 32;
    constexpr int PAD = 20;

    __shared__ unsigned As[2][64][PAD];
    __shared__ unsigned Bs[2][64][PAD];

    const int tid  = threadIdx.x;
    const int warp = tid >> 5;
    const int lane = tid & 31;
    const int mw   = (warp >> 1) * 32;
    const int nw   = (warp & 1) * 32;
    const int n0   = blockIdx.x * 64;
    const int m0   = blockIdx.y * 64;
    const int kb   = blockIdx.z * KC;
    const int N    = gridDim.x * 64;

    const int lr = tid >> 2;
    const int lq = tid & 3;

    float c[2][4][4] = {};

    uint4 a_r[2], w_r[2];
    auto gload = [&](int k0) {
        const int k = kb + k0 + lq * 8;
#pragma unroll
        for (int hh = 0; hh < 2; hh++) {
            const int row = lr + hh * 32;
            const __nv_bfloat16* ap;
            if (CONCAT) {
                ap = (k < 512) ? &A0[(m0 + row) * 512 + k]
                               : &A1[(m0 + row) * 512 + (k - 512)];
            } else {
                ap = &A0[(size_t)(m0 + row) * 512 + k];
            }
            a_r[hh] = *(const uint4*)ap;
            w_r[hh] = *(const uint4*)&W[(size_t)(n0 + row) * KTOT + k];
        }
    };
    auto sstore = [&](int buf) {
#pragma unroll
        for (int hh = 0; hh < 2; hh++) {
            const int row = lr + hh * 32;
            As[buf][row][0 * 4 + lq] = a_r[hh].x;
            As[buf][row][1 * 4 + lq] = a_r[hh].y;
            As[buf][row][2 * 4 + lq] = a_r[hh].z;
            As[buf][row][3 * 4 + lq] = a_r[hh].w;
            Bs[buf][row][0 * 4 + lq] = w_r[hh].x;
            Bs[buf][row][1 * 4 + lq] = w_r[hh].y;
            Bs[buf][row][2 * 4 + lq] = w_r[hh].z;
            Bs[buf][row][3 * 4 + lq] = w_r[hh].w;
        }
    };

    gload(0);
    sstore(0);
    __syncthreads();

    for (int st = 0; st < NST; st++) {
        const bool more = (st + 1 < NST);
        if (more) gload((st + 1) * 32);

        const int cb = st & 1;
#pragma unroll
        for (int s = 0; s < 2; s++) {              // two k16 mma steps per 32-k stage
            const int cidx = ((lane & 3) << 2) + s * 2;
            const int rq = lane >> 2;
            unsigned af[2][4], bfr[4][2];
#pragma unroll
            for (int mt = 0; mt < 2; mt++) {
                const int r = mw + mt * 16 + rq;
                uint2 lo = *(const uint2*)&As[cb][r][cidx];
                uint2 hi = *(const uint2*)&As[cb][r + 8][cidx];
                af[mt][0] = lo.x; af[mt][1] = hi.x;
                af[mt][2] = lo.y; af[mt][3] = hi.y;
            }
#pragma unroll
            for (int nt = 0; nt < 4; nt++) {
                const int nc = nw + nt * 8 + rq;
                uint2 bb = *(const uint2*)&Bs[cb][nc][cidx];
                bfr[nt][0] = bb.x; bfr[nt][1] = bb.y;
            }
#pragma unroll
            for (int mt = 0; mt < 2; mt++)
#pragma unroll
                for (int nt = 0; nt < 4; nt++)
                    mma_bf16(c[mt][nt], af[mt], bfr[nt]);
        }
        if (more) sstore(cb ^ 1);
        __syncthreads();
    }

    // ---------------- epilogue ----------------
#pragma unroll
    for (int mt = 0; mt < 2; mt++) {
#pragma unroll
        for (int nt = 0; nt < 4; nt++) {
            const int m = m0 + mw + mt * 16 + (lane >> 2);
            const int n = n0 + nw + nt * 8 + ((lane & 3) << 1);
            if (EPI == 0) {
                float* dst = part + (size_t)blockIdx.z * 256 * N;
                *(float2*)&dst[(size_t)m * N + n]       = make_float2(c[mt][nt][0], c[mt][nt][1]);
                *(float2*)&dst[(size_t)(m + 8) * N + n] = make_float2(c[mt][nt][2], c[mt][nt][3]);
            } else {
                __nv_bfloat162 p0 = __floats2bfloat162_rn(c[mt][nt][0], c[mt][nt][1]);
                __nv_bfloat162 p1 = __floats2bfloat162_rn(c[mt][nt][2], c[mt][nt][3]);
                *(unsigned*)&g_enc_w1h[(size_t)m * H + n]       = *(unsigned*)&p0;
                *(unsigned*)&g_enc_w1h[(size_t)(m + 8) * H + n] = *(unsigned*)&p1;
            }
        }
    }
}

// ---------------- gates: coalesced float4 partial reduce + FAST activations ---------------
template <bool DEC, int KZ>
__global__ void __launch_bounds__(256) k_gates(
    const float* __restrict__ bias4,
    const float* __restrict__ wiv4,
    const int*   __restrict__ xs,
    const int*   __restrict__ argsort,
    int t)
{
    const int idx = blockIdx.x * 256 + threadIdx.x;
    const int b = idx >> 9;
    const int h = idx & (H - 1);
    const int np = h << 2;
    const int p = t & 1;

    const float xb = DEC ? g_dec_in[p][b] : (float)xs[b * L + t];

    float zx = 0.f, zy = 0.f, zz = 0.f, zw = 0.f;
#pragma unroll
    for (int kz = 0; kz < KZ; kz++) {
        float4 z = *(const float4*)&g_zpart[(size_t)kz * (B * H4) + (size_t)b * H4 + np];
        zx += z.x; zy += z.y; zz += z.z; zw += z.w;
    }
    const float4 bb = *(const float4*)&bias4[np];
    const float4 ww = *(const float4*)&wiv4[np];

    const float zi = zx + bb.x + xb * ww.x;
    const float zf = zy + bb.y + xb * ww.y;
    const float zg = zz + bb.z + xb * ww.z;
    const float zo = zw + bb.w + xb * ww.w;

    const float c  = sigmoid_fast(zf) * g_c[idx] + sigmoid_fast(zi) * tanh_fast(zg);
    const float hn = sigmoid_fast(zo) * tanh_fast(c);
    g_c[idx] = c;
    const __nv_bfloat16 hb = __float2bfloat16_rn(hn);
    g_hh[p ^ 1][idx] = hb;
    if (!DEC) {
        g_enc_outh[((size_t)b * L + t) * H + h] = hb;
    }
    if (DEC && h == 0) {
        g_dec_in[p ^ 1][b] = (float)xs[b * L + argsort[b * L + t]];
    }
}

// ---------------- attention (proven): q-reduce + scores + softmax + context ---------------
__global__ void __launch_bounds__(256) k_attn(const float* __restrict__ vt,
                                              float* __restrict__ out, int t) {
    __shared__ float q_s[H];
    __shared__ float vt_s[H];
    __shared__ float sc[L];
    __shared__ float aj[L];

    const int b = blockIdx.x;
    const int tid = threadIdx.x;
    const int lane = tid & 31;
    const int w = tid >> 5;

    for (int i = tid; i < H; i += 256) {
        float s = 0.0f;
#pragma unroll
        for (int sp = 0; sp < 8; sp++)
            s += g_qpart[(size_t)sp * (B * H) + b * H + i];
        q_s[i]  = s;
        vt_s[i] = vt[i];
    }
    __syncthreads();

#pragma unroll 1
    for (int li = 0; li < 16; li++) {
        const int l = w * 16 + li;
        const uint4* e8 = (const uint4*)(g_enc_w1h + (size_t)(b * L + l) * H);
        float s = 0.f;
#pragma unroll
        for (int j = 0; j < 2; j++) {
            const int base = (lane + j * 32) * 8;
            uint4 u = e8[lane + j * 32];
            float4 q0 = *(const float4*)&q_s[base];
            float4 q1 = *(const float4*)&q_s[base + 4];
            float4 v0 = *(const float4*)&vt_s[base];
            float4 v1 = *(const float4*)&vt_s[base + 4];
            float2 e0 = __bfloat1622float2(*(__nv_bfloat162*)&u.x);
            float2 e1 = __bfloat1622float2(*(__nv_bfloat162*)&u.y);
            float2 e2 = __bfloat1622float2(*(__nv_bfloat162*)&u.z);
            float2 e3 = __bfloat1622float2(*(__nv_bfloat162*)&u.w);
            s += v0.x * tanh_fast(e0.x + q0.x);
            s += v0.y * tanh_fast(e0.y + q0.y);
            s += v0.z * tanh_fast(e1.x + q0.z);
            s += v0.w * tanh_fast(e1.y + q0.w);
            s += v1.x * tanh_fast(e2.x + q1.x);
            s += v1.y * tanh_fast(e2.y + q1.y);
            s += v1.z * tanh_fast(e3.x + q1.z);
            s += v1.w * tanh_fast(e3.y + q1.w);
        }
#pragma unroll
        for (int o = 16; o > 0; o >>= 1) s += __shfl_xor_sync(0xffffffffu, s, o);
        if (lane == 0) sc[l] = s;
    }
    __syncthreads();

    if (w == 0) {
        float sv[4];
        float m = -1e30f;
#pragma unroll
        for (int k = 0; k < 4; k++) { sv[k] = sc[lane * 4 + k]; m = fmaxf(m, sv[k]); }
#pragma unroll
        for (int o = 16; o > 0; o >>= 1) m = fmaxf(m, __shfl_xor_sync(0xffffffffu, m, o));
        float e[4], sum = 0.f;
#pragma unroll
        for (int k = 0; k < 4; k++) { e[k] = __expf(sv[k] - m); sum += e[k]; }
#pragma unroll
        for (int o = 16; o > 0; o >>= 1) sum += __shfl_xor_sync(0xffffffffu, sum, o);
        const float ls  = __logf(sum);
        const float inv = 1.0f / sum;
        float* orow = out + ((size_t)b * L + t) * L;
#pragma unroll
        for (int k = 0; k < 4; k++) {
            orow[lane * 4 + k] = sv[k] - m - ls;
            aj[lane * 4 + k]   = e[k] * inv;
        }
    }
    __syncthreads();

    // context -> bf16 (GEMM operand)
    const int h2 = tid * 2;
    float ax = 0.f, ay = 0.f;
    const __nv_bfloat162* base =
        (const __nv_bfloat162*)(g_enc_outh + (size_t)b * L * H + h2);
#pragma unroll 4
    for (int l = 0; l < L; l++) {
        const float a = aj[l];
        float2 v = __bfloat1622float2(base[(size_t)l * (H / 2)]);
        ax += a * v.x;
        ay += a * v.y;
    }
    __nv_bfloat162 cp = __floats2bfloat162_rn(ax, ay);
    *(__nv_bfloat162*)&g_ctxh[b * H + h2] = cp;
}

}  // namespace

extern "C" void kernel_launch(void* const* d_in, const int* in_sizes, int n_in,
                              void* d_out, int out_size) {
    (void)in_sizes; (void)n_in; (void)out_size;
    const int*   xs      = (const int*)d_in[0];
    const int*   argsort = (const int*)d_in[2];
    const float* enc_Wi  = (const float*)d_in[3];
    const float* enc_Wh  = (const float*)d_in[4];
    const float* enc_b   = (const float*)d_in[5];
    const float* dec_Wi  = (const float*)d_in[6];
    const float* dec_Wh  = (const float*)d_in[7];
    const float* dec_b   = (const float*)d_in[8];
    const float* w1      = (const float*)d_in[9];
    const float* w2      = (const float*)d_in[10];
    const float* vt      = (const float*)d_in[11];
    float* out = (float*)d_out;

    __nv_bfloat16 *p_hh, *p_ctxh, *p_encouth, *p_ew4h, *p_dw4h, *p_w1h, *p_w2h;
    float *p_eb4, *p_ewi4, *p_db4, *p_dwi4, *p_zpart, *p_qpart;
    cudaGetSymbolAddress((void**)&p_hh,      g_hh);
    cudaGetSymbolAddress((void**)&p_ctxh,    g_ctxh);
    cudaGetSymbolAddress((void**)&p_encouth, g_enc_outh);
    cudaGetSymbolAddress((void**)&p_ew4h,    g_ew4h);
    cudaGetSymbolAddress((void**)&p_dw4h,    g_dw4h);
    cudaGetSymbolAddress((void**)&p_w1h,     g_w1h);
    cudaGetSymbolAddress((void**)&p_w2h,     g_w2h);
    cudaGetSymbolAddress((void**)&p_eb4,     g_eb4);
    cudaGetSymbolAddress((void**)&p_ewi4,    g_ewi4);
    cudaGetSymbolAddress((void**)&p_db4,     g_db4);
    cudaGetSymbolAddress((void**)&p_dwi4,    g_dwi4);
    cudaGetSymbolAddress((void**)&p_zpart,   g_zpart);
    cudaGetSymbolAddress((void**)&p_qpart,   g_qpart);

    k_init<<<128, 256>>>();
    k_repack_enc<<<256, 256>>>(enc_Wh, enc_b, enc_Wi);
    k_repack_dec<<<512, 256>>>(dec_Wi, dec_Wh, dec_b);
    k_repack_w<<<256, 256>>>(w1, w2);

    const dim3 gates_grid(B * H / 256);             // 512
    const dim3 lstm_gemm(H4 / 64, B / 64, 4);       // (32, 4, 4) = 512 CTAs
    const dim3 q_gemm(H / 64, B / 64, 8);           // (8, 4, 8)  = 256 CTAs
    const dim3 encw1_grid(H / 64, (B * L) / 64, 1); // (8, 512)

    // ---- encoder: 128 steps of bf16-mma split-K GEMM + gates ----
    for (int t = 0; t < L; t++) {
        const __nv_bfloat16* hp = p_hh + (size_t)(t & 1) * (B * H);
        k_mma<512, 4, false, 0><<<lstm_gemm, 128>>>(p_ew4h, hp, nullptr, p_zpart);
        k_gates<false, 4><<<gates_grid, 256>>>(p_eb4, p_ewi4, xs, nullptr, t);
    }

    // ---- hoisted projection enc_w1 = enc_out @ w1^T (bf16 mma, bf16 out) ----
    k_mma<512, 1, false, 1><<<encw1_grid, 128>>>(p_w1h, p_encouth, nullptr, nullptr);

    // ---- decoder: 128 steps of q-proj -> attention -> LSTM GEMM + gates ----
    for (int t = 0; t < L; t++) {
        const __nv_bfloat16* hp = p_hh + (size_t)(t & 1) * (B * H);
        k_mma<512, 8, false, 0><<<q_gemm, 128>>>(p_w2h, hp, nullptr, p_qpart);
        k_attn<<<B, 256>>>(vt, out, t);
        k_mma<1024, 4, true, 0><<<lstm_gemm, 128>>>(p_dw4h, p_ctxh, hp, p_zpart);
        k_gates<true, 4><<<gates_grid, 256>>>(xs == nullptr ? p_db4 : p_db4, p_dwi4, xs, argsort, t);
    }
}